// round 9
// baseline (speedup 1.0000x reference)
#include <cuda_runtime.h>
#include <math.h>

#define VOCAB 50000
#define EMB 50
#define B 256
#define S 2048
#define L1OUT 2054         // conv1 output length
#define NT 768             // threads per row-CTA
#define NW 24              // warps per row-CTA
#define OPW 86             // outputs per warp (24*86 = 2064 >= 2054)
#define WROWS 92           // window rows per warp (86 + 6 halo)
#define WSTRIDE 740        // per-warp smem stride: 92*7 (sT) + 92 (tokens) + pad
#define FULL 0xffffffffu

// Device-global scratch
__device__ __align__(16) float g_T[VOCAB * 8];  // T[v][0..6]
__device__ float g_part[B];                      // per-row dense output
__device__ unsigned g_ctr = 0;                   // last-CTA counter (wraps -> self-reset)

__device__ __forceinline__ unsigned fmono(float f) {
    unsigned u = __float_as_uint(f);
    return (u & 0x80000000u) ? ~u : (u | 0x80000000u);
}

// ---------------------------------------------------------------------------
// Kernel A: T[v][kw] = dot(emb[v], wmean[kw]); 128 rows/CTA, 512 threads,
// 4 threads per row (cin split 13/13/13/11, 2-level shfl_xor combine).
// ---------------------------------------------------------------------------
__global__ void __launch_bounds__(512) buildT_kernel(
    const float* __restrict__ emb, const float* __restrict__ W1) {
    __shared__ float se[128 * 51];
    __shared__ float wm[7 * 50];

    const int tid  = threadIdx.x;
    const int base = blockIdx.x * 128;
    const int nrows = min(128, VOCAB - base);

    if (tid < 350) {
        float s = 0.f;
        #pragma unroll
        for (int c = 0; c < 6; c++) s += W1[tid * 6 + c];
        wm[tid] = s * (1.f / 6.f);
    }
    const float2* e2 = (const float2*)(emb + (size_t)base * EMB);
    for (int i = tid; i < nrows * 25; i += 512) {
        int row = i / 25;
        int c2  = i - row * 25;
        float2 v = e2[row * 25 + c2];
        se[row * 51 + 2 * c2]     = v.x;
        se[row * 51 + 2 * c2 + 1] = v.y;
    }
    __syncthreads();

    const int row = tid >> 2;
    const int sub = tid & 3;
    const int c0  = sub * 13;
    const int c1  = (sub == 3) ? 50 : c0 + 13;

    float acc[7] = {0.f, 0.f, 0.f, 0.f, 0.f, 0.f, 0.f};
    if (row < nrows) {
        const float* er = se + row * 51;
        for (int cin = c0; cin < c1; cin++) {
            float e = er[cin];
            #pragma unroll
            for (int kw = 0; kw < 7; kw++) acc[kw] += e * wm[kw * EMB + cin];
        }
    }
    // combine across the 4-lane group (all lanes participate: shfl mask FULL)
    #pragma unroll
    for (int kw = 0; kw < 7; kw++) {
        acc[kw] += __shfl_xor_sync(FULL, acc[kw], 1);
        acc[kw] += __shfl_xor_sync(FULL, acc[kw], 2);
    }
    if (row < nrows && sub == 0) {
        float4* d = (float4*)(g_T + (size_t)(base + row) * 8);
        d[0] = make_float4(acc[0], acc[1], acc[2], acc[3]);
        d[1] = make_float4(acc[4], acc[5], acc[6], 0.f);
    }
}

// ---------------------------------------------------------------------------
// Kernel B: one CTA (768 thr) per batch row. Warp-local windows: each warp
// gathers its 92 T-rows, computes 86 excitements + local top-8 with NO block
// barriers. 3 block barriers total. Fused last-CTA reduction.
// ---------------------------------------------------------------------------
__global__ void __launch_bounds__(NT, 2) dcnn_row_kernel(
    const int*   __restrict__ x,
    const float* __restrict__ emb,
    const float* __restrict__ W1, const float* __restrict__ b1,
    const float* __restrict__ W2, const float* __restrict__ b2,
    const float* __restrict__ Wd, const float* __restrict__ bd,
    float* __restrict__ out) {

    extern __shared__ float sm[];
    float*    wbase_sm = sm;                         // 24 * WSTRIDE (warp windows)
    unsigned* cand_u = (unsigned*)(sm + NW * WSTRIDE); // 192
    int*      cand_t = (int*)(cand_u + 192);         // 192
    int*      idx8s  = cand_t + 192;                 // 8
    float*    s1p    = (float*)(idx8s + 8);          // 96 (16x6 zero-padded)
    float*    out2s  = s1p + 96;                     // 168 (12x14)
    float*    sW1    = out2s + 168;                  // 2100

    const int tid  = threadIdx.x;
    const int lane = tid & 31;
    const int wid  = tid >> 5;
    const int b    = blockIdx.x;
    const int* xr  = x + (size_t)b * S;

    // Early staging (no barrier needed until B1)
    #pragma unroll
    for (int k = 0; k < 3; k++) {
        int i = tid + k * NT;
        if (i < 2100) sW1[i] = W1[i];
    }
    if (tid < 96) s1p[tid] = 0.f;

    // ---- Warp-local region
    float* swin  = wbase_sm + wid * WSTRIDE;         // 92*7 T values
    int*   stokw = (int*)(swin + WROWS * 7);         // 92 tokens
    const int t0  = wid * OPW;                        // first output of this warp
    const int cnt = min(OPW, L1OUT - t0);             // 86 (last warp 76)

    // tokens for window rows r in [0, 92): global p = t0 - 6 + r
    #pragma unroll
    for (int k = 0; k < 3; k++) {
        int r = lane + 32 * k;
        if (r < WROWS) {
            int p = t0 - 6 + r;
            stokw[r] = ((unsigned)p < (unsigned)S) ? xr[p] : -1;
        }
    }
    __syncwarp();

    // cooperative 8-lane T gather: 4 rows per iteration
    const int col  = lane & 7;
    const int rsub = lane >> 3;
    #pragma unroll
    for (int j = 0; j < 23; j++) {
        int r = 4 * j + rsub;                        // 0..91
        int tok = stokw[r];
        float v = (tok >= 0) ? g_T[(size_t)tok * 8 + col] : 0.f;
        if (col < 7) swin[r * 7 + col] = v;
    }
    __syncwarp();

    // excitements (halo rows are zero -> no predicates inside)
    unsigned evu[3];
    #pragma unroll
    for (int k = 0; k < 3; k++) {
        int tl = lane + 32 * k;
        unsigned u = 0u;
        if (tl < cnt) {
            float s = 0.f;
            #pragma unroll
            for (int kw = 0; kw < 7; kw++) s += swin[(tl + kw) * 7 + kw];
            u = fmono(s);
        }
        evu[k] = u;
    }

    // warp-local top-8 via REDUX (value desc, global index asc on ties)
    #pragma unroll
    for (int r = 0; r < 8; r++) {
        unsigned bu = 0u; int bt = 0x7fffffff; int bk = 0;
        #pragma unroll
        for (int k = 0; k < 3; k++)
            if (evu[k] > bu) { bu = evu[k]; bt = t0 + lane + 32 * k; bk = k; }
        unsigned m = __reduce_max_sync(FULL, bu);
        int tw = (bu == m) ? bt : 0x7fffffff;
        int tmin = __reduce_min_sync(FULL, tw);
        bool win = (bu == m) && (bt == tmin);
        #pragma unroll
        for (int k = 0; k < 3; k++)
            if (win && k == bk) evu[k] = 0u;
        if (lane == 0) { cand_u[wid * 8 + r] = m; cand_t[wid * 8 + r] = tmin; }
    }
    __syncthreads();                                 // B1: candidates + W1 + s1p

    // ---- warp 0 merges 192 candidates -> global ordered top-8
    if (wid == 0) {
        unsigned cu[6]; int ct[6];
        #pragma unroll
        for (int j = 0; j < 6; j++) {
            cu[j] = cand_u[lane + 32 * j];
            ct[j] = cand_t[lane + 32 * j];
        }
        #pragma unroll
        for (int r = 0; r < 8; r++) {
            unsigned bu = 0u; int bt = 0x7fffffff; int bj = 0;
            #pragma unroll
            for (int j = 0; j < 6; j++)
                if (cu[j] > bu || (cu[j] == bu && ct[j] < bt)) {
                    bu = cu[j]; bt = ct[j]; bj = j;
                }
            unsigned m = __reduce_max_sync(FULL, bu);
            int tw = (bu == m) ? bt : 0x7fffffff;
            int tmin = __reduce_min_sync(FULL, tw);
            bool win = (bu == m) && (bt == tmin);
            #pragma unroll
            for (int j = 0; j < 6; j++)
                if (win && j == bj) cu[j] = 0u;
            if (lane == 0) idx8s[r] = tmin;
        }
    }
    __syncthreads();                                 // B2: idx8s ready

    // ---- conv1 at the 8 selected positions (warp i -> position i)
    if (wid < 8) {
        int pos = idx8s[wid];
        int tkn = -1;
        if (lane < 7) {
            int p = pos - 6 + lane;
            tkn = ((unsigned)p < (unsigned)S) ? xr[p] : -1;
        }
        float acc[6] = {0.f, 0.f, 0.f, 0.f, 0.f, 0.f};
        #pragma unroll
        for (int k = 0; k < 11; k++) {
            int rr = lane + 32 * k;
            bool ok = rr < 350;
            int rr2 = ok ? rr : 0;
            int kw = rr2 / 50;
            int cin = rr2 - kw * 50;
            int t = __shfl_sync(FULL, tkn, kw);
            float e = (ok && t >= 0) ? emb[(size_t)t * EMB + cin] : 0.f;
            #pragma unroll
            for (int c = 0; c < 6; c++) acc[c] += e * sW1[rr2 * 6 + c];
        }
        #pragma unroll
        for (int c = 0; c < 6; c++) {
            #pragma unroll
            for (int o = 16; o > 0; o >>= 1)
                acc[c] += __shfl_xor_sync(FULL, acc[c], o);  // all lanes: full sum
        }
        if (lane < 6) {
            float a = acc[0];
            a = (lane == 1) ? acc[1] : a;
            a = (lane == 2) ? acc[2] : a;
            a = (lane == 3) ? acc[3] : a;
            a = (lane == 4) ? acc[4] : a;
            a = (lane == 5) ? acc[5] : a;
            s1p[(4 + wid) * 6 + lane] = 1.f / (1.f + expf(-(a + b1[lane])));
        }
    }
    __syncthreads();                                 // B3: s1p ready (last barrier)

    // ---- Tail: warp 0 only
    if (wid == 0) {
        #pragma unroll
        for (int j = 0; j < 6; j++) {
            int idx = lane + 32 * j;
            if (idx < 168) {
                int t2 = idx / 14, c2 = idx - t2 * 14;
                float a = b2[c2];
                #pragma unroll
                for (int kw2 = 0; kw2 < 5; kw2++)
                    #pragma unroll
                    for (int cin = 0; cin < 6; cin++)
                        a += s1p[(t2 + kw2) * 6 + cin] * W2[(kw2 * 6 + cin) * 14 + c2];
                out2s[idx] = a;
            }
        }
        __syncwarp();
        float e2 = 0.f;
        if (lane < 12) {
            #pragma unroll
            for (int c = 0; c < 14; c++) e2 += out2s[lane * 14 + c];
        }
        unsigned e2u = (lane < 12) ? fmono(e2) : 0u;
        int j4r[4];
        #pragma unroll
        for (int r = 0; r < 4; r++) {
            unsigned m = __reduce_max_sync(FULL, e2u);
            int tw = (e2u == m) ? lane : 63;
            int tmin = __reduce_min_sync(FULL, tw);
            j4r[r] = tmin;
            if (lane == tmin) e2u = 0u;
        }
        float mm = 0.f;
        if (lane < 14)
            mm = 0.25f * (out2s[j4r[0] * 14 + lane] + out2s[j4r[1] * 14 + lane] +
                          out2s[j4r[2] * 14 + lane] + out2s[j4r[3] * 14 + lane]) * Wd[lane];
        #pragma unroll
        for (int o = 16; o > 0; o >>= 1) mm += __shfl_xor_sync(FULL, mm, o);

        unsigned old = 0;
        if (lane == 0) {
            g_part[b] = mm + bd[0];
            __threadfence();
            old = atomicInc(&g_ctr, B - 1);          // wraps -> self-reset each replay
        }
        old = __shfl_sync(FULL, old, 0);
        if (old == B - 1) {
            __threadfence();
            float s = 0.f;
            #pragma unroll
            for (int k = 0; k < 8; k++) s += g_part[lane + 32 * k];
            #pragma unroll
            for (int o = 16; o > 0; o >>= 1) s += __shfl_xor_sync(FULL, s, o);
            if (lane == 0) out[0] = 1.f / (1.f + expf(-(s * (1.f / 256.f))));
        }
    }
}

// ---------------------------------------------------------------------------
extern "C" void kernel_launch(void* const* d_in, const int* in_sizes, int n_in,
                              void* d_out, int out_size) {
    const int*   x    = (const int*)  d_in[0];
    const float* emb  = (const float*)d_in[1];
    const float* W1   = (const float*)d_in[2];
    const float* b1   = (const float*)d_in[3];
    const float* W2   = (const float*)d_in[4];
    const float* b2   = (const float*)d_in[5];
    const float* Wd   = (const float*)d_in[6];
    const float* bd   = (const float*)d_in[7];
    float* out = (float*)d_out;

    const size_t smemB = (NW * WSTRIDE + 192 + 192 + 8 + 96 + 168 + 2100)
                         * sizeof(float);                                 // ~82 KB
    cudaFuncSetAttribute(dcnn_row_kernel,
                         cudaFuncAttributeMaxDynamicSharedMemorySize, (int)smemB);

    buildT_kernel<<<(VOCAB + 127) / 128, 512>>>(emb, W1);
    dcnn_row_kernel<<<B, NT, smemB>>>(x, emb, W1, b1, W2, b2, Wd, bd, out);
    (void)in_sizes; (void)n_in; (void)out_size;
}

// round 10
// speedup vs baseline: 1.0708x; 1.0708x over previous
#include <cuda_runtime.h>
#include <math.h>

#define VOCAB 50000
#define EMB 50
#define B 256
#define S 2048
#define L1OUT 2054         // conv1 output length
#define NT 768             // threads per row-CTA
#define NW 24              // warps per row-CTA
#define OPW 86             // outputs per warp (24*86 = 2064 >= 2054)
#define WROWS 92           // window rows per warp (86 + 6 halo)
#define WSTRIDE 740        // per-warp smem stride: 92*7 (sT) + 92 (tokens) + pad
#define FULL 0xffffffffu

// Device-global scratch
__device__ __align__(16) float g_T[VOCAB * 8];  // T[v][0..6]
__device__ float g_part[B];                      // per-row dense output
__device__ unsigned g_ctr = 0;                   // last-CTA counter (wraps -> self-reset)

__device__ __forceinline__ unsigned fmono(float f) {
    unsigned u = __float_as_uint(f);
    return (u & 0x80000000u) ? ~u : (u | 0x80000000u);
}

// ---------------------------------------------------------------------------
// Kernel A: T[v][kw] = dot(emb[v], wmean[kw]). 128 vocab rows per CTA,
// float2-vectorized coalesced staging into smem (stride-51: conflict-free).
// (R6 proven version.)
// ---------------------------------------------------------------------------
__global__ void __launch_bounds__(128) buildT_kernel(
    const float* __restrict__ emb, const float* __restrict__ W1) {
    __shared__ float se[128 * 51];
    __shared__ float wm[7 * 50];

    const int tid  = threadIdx.x;
    const int base = blockIdx.x * 128;
    const int nrows = min(128, VOCAB - base);

    for (int i = tid; i < 350; i += 128) {
        float s = 0.f;
        #pragma unroll
        for (int c = 0; c < 6; c++) s += W1[i * 6 + c];
        wm[i] = s * (1.f / 6.f);
    }
    const float2* e2 = (const float2*)(emb + (size_t)base * EMB);
    for (int i = tid; i < nrows * 25; i += 128) {
        int row = i / 25;
        int c2  = i - row * 25;
        float2 v = e2[row * 25 + c2];
        se[row * 51 + 2 * c2]     = v.x;
        se[row * 51 + 2 * c2 + 1] = v.y;
    }
    __syncthreads();

    if (tid >= nrows) return;
    const float* er = se + tid * 51;
    float acc[7] = {0.f, 0.f, 0.f, 0.f, 0.f, 0.f, 0.f};
    #pragma unroll 10
    for (int cin = 0; cin < EMB; cin++) {
        float e = er[cin];
        #pragma unroll
        for (int kw = 0; kw < 7; kw++) acc[kw] += e * wm[kw * EMB + cin];
    }
    float4* d = (float4*)(g_T + (size_t)(base + tid) * 8);
    d[0] = make_float4(acc[0], acc[1], acc[2], acc[3]);
    d[1] = make_float4(acc[4], acc[5], acc[6], 0.f);
}

// ---------------------------------------------------------------------------
// Kernel B: one CTA (768 thr) per batch row. Warp-local windows; float4
// 2-lane T gather (16 rows per LDG.128); REDUX top-8; 3 block barriers;
// fused last-CTA reduction.
// ---------------------------------------------------------------------------
__global__ void __launch_bounds__(NT, 2) dcnn_row_kernel(
    const int*   __restrict__ x,
    const float* __restrict__ emb,
    const float* __restrict__ W1, const float* __restrict__ b1,
    const float* __restrict__ W2, const float* __restrict__ b2,
    const float* __restrict__ Wd, const float* __restrict__ bd,
    float* __restrict__ out) {

    extern __shared__ float sm[];
    float*    wbase_sm = sm;                           // 24 * WSTRIDE warp windows
    unsigned* cand_u = (unsigned*)(sm + NW * WSTRIDE); // 192
    int*      cand_t = (int*)(cand_u + 192);           // 192
    int*      idx8s  = cand_t + 192;                   // 8
    float*    s1p    = (float*)(idx8s + 8);            // 96 (16x6 zero-padded)
    float*    out2s  = s1p + 96;                       // 168 (12x14)
    float*    sW1    = out2s + 168;                    // 2100

    const int tid  = threadIdx.x;
    const int lane = tid & 31;
    const int wid  = tid >> 5;
    const int b    = blockIdx.x;
    const int* xr  = x + (size_t)b * S;

    // Early staging (needed only after B1)
    #pragma unroll
    for (int k = 0; k < 3; k++) {
        int i = tid + k * NT;
        if (i < 2100) sW1[i] = W1[i];
    }
    if (tid < 96) s1p[tid] = 0.f;

    // ---- Warp-local region
    float* swin  = wbase_sm + wid * WSTRIDE;           // 92*7 T values (stride 7)
    int*   stokw = (int*)(swin + WROWS * 7);           // 92 tokens
    const int t0  = wid * OPW;                          // first output of this warp
    const int cnt = min(OPW, L1OUT - t0);               // 86 (last warp 76)

    // tokens for window rows r in [0, 92): global p = t0 - 6 + r
    #pragma unroll
    for (int k = 0; k < 3; k++) {
        int r = lane + 32 * k;
        if (r < WROWS) {
            int p = t0 - 6 + r;
            stokw[r] = ((unsigned)p < (unsigned)S) ? xr[p] : -1;
        }
    }
    __syncwarp();

    // float4 2-lane T gather: 16 rows per iteration (6 iters vs 23 for LDG.32)
    {
        const int col  = lane & 1;                     // float4 half: 0 -> T[0..3], 1 -> T[4..7]
        const int rsub = lane >> 1;                    // 0..15
        #pragma unroll
        for (int j = 0; j < 6; j++) {
            int r = j * 16 + rsub;                     // 0..95
            if (r < WROWS) {
                int tok = stokw[r];
                float4 v = (tok >= 0)
                    ? *(const float4*)(g_T + (size_t)tok * 8 + col * 4)
                    : make_float4(0.f, 0.f, 0.f, 0.f);
                float* dst = swin + r * 7 + col * 4;
                int e0 = col * 4;
                dst[0] = v.x;                          // elements 0/4
                dst[1] = v.y;                          // 1/5
                dst[2] = v.z;                          // 2/6
                if (e0 + 3 < 7) dst[3] = v.w;          // 3 (skip 7)
            }
        }
    }
    __syncwarp();

    // excitements (halo rows are zero -> no predicates inside)
    unsigned evu[3];
    #pragma unroll
    for (int k = 0; k < 3; k++) {
        int tl = lane + 32 * k;
        unsigned u = 0u;
        if (tl < cnt) {
            float s = 0.f;
            #pragma unroll
            for (int kw = 0; kw < 7; kw++) s += swin[(tl + kw) * 7 + kw];
            u = fmono(s);
        }
        evu[k] = u;
    }

    // warp-local top-8 via REDUX (value desc, global index asc on ties)
    #pragma unroll
    for (int r = 0; r < 8; r++) {
        unsigned bu = 0u; int bt = 0x7fffffff; int bk = 0;
        #pragma unroll
        for (int k = 0; k < 3; k++)
            if (evu[k] > bu) { bu = evu[k]; bt = t0 + lane + 32 * k; bk = k; }
        unsigned m = __reduce_max_sync(FULL, bu);
        int tw = (bu == m) ? bt : 0x7fffffff;
        int tmin = __reduce_min_sync(FULL, tw);
        bool win = (bu == m) && (bt == tmin);
        #pragma unroll
        for (int k = 0; k < 3; k++)
            if (win && k == bk) evu[k] = 0u;
        if (lane == 0) { cand_u[wid * 8 + r] = m; cand_t[wid * 8 + r] = tmin; }
    }
    __syncthreads();                                   // B1: candidates + W1 + s1p

    // ---- warp 0 merges 192 candidates -> global ordered top-8
    if (wid == 0) {
        unsigned cu[6]; int ct[6];
        #pragma unroll
        for (int j = 0; j < 6; j++) {
            cu[j] = cand_u[lane + 32 * j];
            ct[j] = cand_t[lane + 32 * j];
        }
        #pragma unroll
        for (int r = 0; r < 8; r++) {
            unsigned bu = 0u; int bt = 0x7fffffff; int bj = 0;
            #pragma unroll
            for (int j = 0; j < 6; j++)
                if (cu[j] > bu || (cu[j] == bu && ct[j] < bt)) {
                    bu = cu[j]; bt = ct[j]; bj = j;
                }
            unsigned m = __reduce_max_sync(FULL, bu);
            int tw = (bu == m) ? bt : 0x7fffffff;
            int tmin = __reduce_min_sync(FULL, tw);
            bool win = (bu == m) && (bt == tmin);
            #pragma unroll
            for (int j = 0; j < 6; j++)
                if (win && j == bj) cu[j] = 0u;
            if (lane == 0) idx8s[r] = tmin;
        }
    }
    __syncthreads();                                   // B2: idx8s ready

    // ---- conv1 at the 8 selected positions (warp i -> position i)
    if (wid < 8) {
        int pos = idx8s[wid];
        int tkn = -1;
        if (lane < 7) {
            int p = pos - 6 + lane;
            tkn = ((unsigned)p < (unsigned)S) ? xr[p] : -1;
        }
        float acc[6] = {0.f, 0.f, 0.f, 0.f, 0.f, 0.f};
        #pragma unroll
        for (int k = 0; k < 11; k++) {
            int rr = lane + 32 * k;
            bool ok = rr < 350;
            int rr2 = ok ? rr : 0;
            int kw = rr2 / 50;
            int cin = rr2 - kw * 50;
            int t = __shfl_sync(FULL, tkn, kw);
            float e = (ok && t >= 0) ? emb[(size_t)t * EMB + cin] : 0.f;
            #pragma unroll
            for (int c = 0; c < 6; c++) acc[c] += e * sW1[rr2 * 6 + c];
        }
        #pragma unroll
        for (int c = 0; c < 6; c++) {
            #pragma unroll
            for (int o = 16; o > 0; o >>= 1)
                acc[c] += __shfl_xor_sync(FULL, acc[c], o);  // all lanes: full sum
        }
        if (lane < 6) {
            float a = acc[0];
            a = (lane == 1) ? acc[1] : a;
            a = (lane == 2) ? acc[2] : a;
            a = (lane == 3) ? acc[3] : a;
            a = (lane == 4) ? acc[4] : a;
            a = (lane == 5) ? acc[5] : a;
            s1p[(4 + wid) * 6 + lane] = 1.f / (1.f + expf(-(a + b1[lane])));
        }
    }
    __syncthreads();                                   // B3: s1p ready (last barrier)

    // ---- Tail: warp 0 only
    if (wid == 0) {
        #pragma unroll
        for (int j = 0; j < 6; j++) {
            int idx = lane + 32 * j;
            if (idx < 168) {
                int t2 = idx / 14, c2 = idx - t2 * 14;
                float a = b2[c2];
                #pragma unroll
                for (int kw2 = 0; kw2 < 5; kw2++)
                    #pragma unroll
                    for (int cin = 0; cin < 6; cin++)
                        a += s1p[(t2 + kw2) * 6 + cin] * W2[(kw2 * 6 + cin) * 14 + c2];
                out2s[idx] = a;
            }
        }
        __syncwarp();
        float e2 = 0.f;
        if (lane < 12) {
            #pragma unroll
            for (int c = 0; c < 14; c++) e2 += out2s[lane * 14 + c];
        }
        unsigned e2u = (lane < 12) ? fmono(e2) : 0u;
        int j4r[4];
        #pragma unroll
        for (int r = 0; r < 4; r++) {
            unsigned m = __reduce_max_sync(FULL, e2u);
            int tw = (e2u == m) ? lane : 63;
            int tmin = __reduce_min_sync(FULL, tw);
            j4r[r] = tmin;
            if (lane == tmin) e2u = 0u;
        }
        float mm = 0.f;
        if (lane < 14)
            mm = 0.25f * (out2s[j4r[0] * 14 + lane] + out2s[j4r[1] * 14 + lane] +
                          out2s[j4r[2] * 14 + lane] + out2s[j4r[3] * 14 + lane]) * Wd[lane];
        #pragma unroll
        for (int o = 16; o > 0; o >>= 1) mm += __shfl_xor_sync(FULL, mm, o);

        unsigned old = 0;
        if (lane == 0) {
            g_part[b] = mm + bd[0];
            __threadfence();
            old = atomicInc(&g_ctr, B - 1);            // wraps -> self-reset each replay
        }
        old = __shfl_sync(FULL, old, 0);
        if (old == B - 1) {
            __threadfence();
            float s = 0.f;
            #pragma unroll
            for (int k = 0; k < 8; k++) s += g_part[lane + 32 * k];
            #pragma unroll
            for (int o = 16; o > 0; o >>= 1) s += __shfl_xor_sync(FULL, s, o);
            if (lane == 0) out[0] = 1.f / (1.f + expf(-(s * (1.f / 256.f))));
        }
    }
}

// ---------------------------------------------------------------------------
extern "C" void kernel_launch(void* const* d_in, const int* in_sizes, int n_in,
                              void* d_out, int out_size) {
    const int*   x    = (const int*)  d_in[0];
    const float* emb  = (const float*)d_in[1];
    const float* W1   = (const float*)d_in[2];
    const float* b1   = (const float*)d_in[3];
    const float* W2   = (const float*)d_in[4];
    const float* b2   = (const float*)d_in[5];
    const float* Wd   = (const float*)d_in[6];
    const float* bd   = (const float*)d_in[7];
    float* out = (float*)d_out;

    const size_t smemB = (NW * WSTRIDE + 192 + 192 + 8 + 96 + 168 + 2100)
                         * sizeof(float);                                 // ~82 KB
    cudaFuncSetAttribute(dcnn_row_kernel,
                         cudaFuncAttributeMaxDynamicSharedMemorySize, (int)smemB);

    buildT_kernel<<<(VOCAB + 127) / 128, 128>>>(emb, W1);
    dcnn_row_kernel<<<B, NT, smemB>>>(x, emb, W1, b1, W2, b2, Wd, bd, out);
    (void)in_sizes; (void)n_in; (void)out_size;
}

// round 11
// speedup vs baseline: 1.1029x; 1.0299x over previous
#include <cuda_runtime.h>
#include <math.h>

#define VOCAB 50000
#define EMB 50
#define B 256
#define S 2048
#define L1OUT 2054         // conv1 output length
#define NT 768             // threads per row-CTA
#define NW 24              // warps per row-CTA
#define OPW 86             // outputs per warp (24*86 = 2064 >= 2054)
#define WROWS 92           // window rows per warp (86 + 6 halo)
#define WSTRIDE 740        // per-warp smem stride: 92*7 (sT) + 92 (tokens) + pad
#define VROWS 196          // vocab rows per CTA for fused buildT (256*196 >= 50000)
#define FULL 0xffffffffu

// Device-global scratch
__device__ __align__(16) float g_T[VOCAB * 8];  // T[v][0..6]
__device__ float g_part[B];                      // per-row dense output
__device__ unsigned g_ctr  = 0;                  // last-CTA counter (wraps -> self-reset)
__device__ unsigned g_done = 0;                  // buildT arrival counter (monotonic)

__device__ __forceinline__ unsigned fmono(float f) {
    unsigned u = __float_as_uint(f);
    return (u & 0x80000000u) ? ~u : (u | 0x80000000u);
}

// ---------------------------------------------------------------------------
// Fused kernel: per-CTA buildT slice -> grid release barrier -> dcnn pipeline.
// One CTA (768 thr) per batch row; single co-resident wave (proven by
// launch_bounds(768,2): 296 slots >= 256 CTAs) makes the spin deadlock-free.
// ---------------------------------------------------------------------------
__global__ void __launch_bounds__(NT, 2) dcnn_fused_kernel(
    const int*   __restrict__ x,
    const float* __restrict__ emb,
    const float* __restrict__ W1, const float* __restrict__ b1,
    const float* __restrict__ W2, const float* __restrict__ b2,
    const float* __restrict__ Wd, const float* __restrict__ bd,
    float* __restrict__ out) {

    extern __shared__ float sm[];
    float*    wbase_sm = sm;                           // 24*WSTRIDE warp windows
    unsigned* cand_u = (unsigned*)(sm + NW * WSTRIDE); // 192
    int*      cand_t = (int*)(cand_u + 192);           // 192
    int*      idx8s  = cand_t + 192;                   // 8
    float*    s1p    = (float*)(idx8s + 8);            // 96 (16x6 zero-padded)
    float*    out2s  = s1p + 96;                       // 168 (12x14)
    float*    sW1    = out2s + 168;                    // 2100 (holds wm first)

    const int tid  = threadIdx.x;
    const int lane = tid & 31;
    const int wid  = tid >> 5;
    const int b    = blockIdx.x;
    const int* xr  = x + (size_t)b * S;

    // ============== Fused buildT: this CTA's 196 vocab rows ==============
    {
        float* se = wbase_sm;                          // 196*51 = 9996 floats
        const int vbase = b * VROWS;
        const int nrows = min(VROWS, VOCAB - vbase);   // last CTA: 20

        if (tid < 350) {                               // wm into sW1 (temp)
            float s = 0.f;
            #pragma unroll
            for (int c = 0; c < 6; c++) s += W1[tid * 6 + c];
            sW1[tid] = s * (1.f / 6.f);
        }
        // coalesced float2 staging of emb rows (stride-51 pad)
        const float2* e2 = (const float2*)(emb + (size_t)vbase * EMB);
        for (int i = tid; i < nrows * 25; i += NT) {
            int row = i / 25;
            int c2  = i - row * 25;
            float2 v = e2[row * 25 + c2];
            se[row * 51 + 2 * c2]     = v.x;
            se[row * 51 + 2 * c2 + 1] = v.y;
        }
        __syncthreads();                               // wm + se ready

        if (tid < nrows) {                             // identical order to proven buildT
            const float* er = se + tid * 51;
            float acc[7] = {0.f, 0.f, 0.f, 0.f, 0.f, 0.f, 0.f};
            #pragma unroll 10
            for (int cin = 0; cin < EMB; cin++) {
                float e = er[cin];
                #pragma unroll
                for (int kw = 0; kw < 7; kw++) acc[kw] += e * sW1[kw * EMB + cin];
            }
            float4* d = (float4*)(g_T + (size_t)(vbase + tid) * 8);
            d[0] = make_float4(acc[0], acc[1], acc[2], acc[3]);
            d[1] = make_float4(acc[4], acc[5], acc[6], 0.f);
        }
        __threadfence();                               // make g_T writes visible (gpu scope)
        __syncthreads();                               // all writers done; se region free
    }

    // Arrive (tid0 keeps its target in a register)
    unsigned target = 0;
    if (tid == 0) {
        unsigned old = atomicAdd(&g_done, 1u);         // monotonic across replays
        target = (old / (unsigned)B + 1u) * (unsigned)B;
    }

    // ====== Overlap zone: staging that does NOT need g_T ======
    #pragma unroll
    for (int k = 0; k < 3; k++) {                      // W1 (overwrites wm)
        int i = tid + k * NT;
        if (i < 2100) sW1[i] = W1[i];
    }
    if (tid < 96) s1p[tid] = 0.f;

    float* swin  = wbase_sm + wid * WSTRIDE;           // 92*7 T values (stride 7)
    int*   stokw = (int*)(swin + WROWS * 7);           // 92 tokens
    const int t0  = wid * OPW;
    const int cnt = min(OPW, L1OUT - t0);

    #pragma unroll
    for (int k = 0; k < 3; k++) {                      // window tokens
        int r = lane + 32 * k;
        if (r < WROWS) {
            int p = t0 - 6 + r;
            stokw[r] = ((unsigned)p < (unsigned)S) ? xr[p] : -1;
        }
    }

    // ====== Grid release: wait until all 256 CTAs finished their T slice ======
    if (tid == 0) {
        volatile unsigned* p = &g_done;
        while (*p < target) __nanosleep(64);
        __threadfence();                               // acquire
    }
    __syncthreads();                                   // B0: g_T globally ready

    // ============== dcnn pipeline (identical to proven R10) ==============
    // float4 2-lane T gather: 16 rows per iteration
    {
        const int col  = lane & 1;
        const int rsub = lane >> 1;
        #pragma unroll
        for (int j = 0; j < 6; j++) {
            int r = j * 16 + rsub;
            if (r < WROWS) {
                int tok = stokw[r];
                float4 v = (tok >= 0)
                    ? *(const float4*)(g_T + (size_t)tok * 8 + col * 4)
                    : make_float4(0.f, 0.f, 0.f, 0.f);
                float* dst = swin + r * 7 + col * 4;
                dst[0] = v.x;
                dst[1] = v.y;
                dst[2] = v.z;
                if (col == 0) dst[3] = v.w;            // skip element 7
            }
        }
    }
    __syncwarp();

    // excitements (halo rows are zero -> no predicates inside)
    unsigned evu[3];
    #pragma unroll
    for (int k = 0; k < 3; k++) {
        int tl = lane + 32 * k;
        unsigned u = 0u;
        if (tl < cnt) {
            float s = 0.f;
            #pragma unroll
            for (int kw = 0; kw < 7; kw++) s += swin[(tl + kw) * 7 + kw];
            u = fmono(s);
        }
        evu[k] = u;
    }

    // warp-local top-8 via REDUX (value desc, global index asc on ties)
    #pragma unroll
    for (int r = 0; r < 8; r++) {
        unsigned bu = 0u; int bt = 0x7fffffff; int bk = 0;
        #pragma unroll
        for (int k = 0; k < 3; k++)
            if (evu[k] > bu) { bu = evu[k]; bt = t0 + lane + 32 * k; bk = k; }
        unsigned m = __reduce_max_sync(FULL, bu);
        int tw = (bu == m) ? bt : 0x7fffffff;
        int tmin = __reduce_min_sync(FULL, tw);
        bool win = (bu == m) && (bt == tmin);
        #pragma unroll
        for (int k = 0; k < 3; k++)
            if (win && k == bk) evu[k] = 0u;
        if (lane == 0) { cand_u[wid * 8 + r] = m; cand_t[wid * 8 + r] = tmin; }
    }
    __syncthreads();                                   // B1: candidates ready

    // warp 0 merges 192 candidates -> global ordered top-8
    if (wid == 0) {
        unsigned cu[6]; int ct[6];
        #pragma unroll
        for (int j = 0; j < 6; j++) {
            cu[j] = cand_u[lane + 32 * j];
            ct[j] = cand_t[lane + 32 * j];
        }
        #pragma unroll
        for (int r = 0; r < 8; r++) {
            unsigned bu = 0u; int bt = 0x7fffffff; int bj = 0;
            #pragma unroll
            for (int j = 0; j < 6; j++)
                if (cu[j] > bu || (cu[j] == bu && ct[j] < bt)) {
                    bu = cu[j]; bt = ct[j]; bj = j;
                }
            unsigned m = __reduce_max_sync(FULL, bu);
            int tw = (bu == m) ? bt : 0x7fffffff;
            int tmin = __reduce_min_sync(FULL, tw);
            bool win = (bu == m) && (bt == tmin);
            #pragma unroll
            for (int j = 0; j < 6; j++)
                if (win && j == bj) cu[j] = 0u;
            if (lane == 0) idx8s[r] = tmin;
        }
    }
    __syncthreads();                                   // B2: idx8s ready

    // conv1 at the 8 selected positions (warp i -> position i)
    if (wid < 8) {
        int pos = idx8s[wid];
        int tkn = -1;
        if (lane < 7) {
            int p = pos - 6 + lane;
            tkn = ((unsigned)p < (unsigned)S) ? xr[p] : -1;
        }
        float acc[6] = {0.f, 0.f, 0.f, 0.f, 0.f, 0.f};
        #pragma unroll
        for (int k = 0; k < 11; k++) {
            int rr = lane + 32 * k;
            bool ok = rr < 350;
            int rr2 = ok ? rr : 0;
            int kw = rr2 / 50;
            int cin = rr2 - kw * 50;
            int t = __shfl_sync(FULL, tkn, kw);
            float e = (ok && t >= 0) ? emb[(size_t)t * EMB + cin] : 0.f;
            #pragma unroll
            for (int c = 0; c < 6; c++) acc[c] += e * sW1[rr2 * 6 + c];
        }
        #pragma unroll
        for (int c = 0; c < 6; c++) {
            #pragma unroll
            for (int o = 16; o > 0; o >>= 1)
                acc[c] += __shfl_xor_sync(FULL, acc[c], o);  // all lanes: full sum
        }
        if (lane < 6) {
            float a = acc[0];
            a = (lane == 1) ? acc[1] : a;
            a = (lane == 2) ? acc[2] : a;
            a = (lane == 3) ? acc[3] : a;
            a = (lane == 4) ? acc[4] : a;
            a = (lane == 5) ? acc[5] : a;
            s1p[(4 + wid) * 6 + lane] = 1.f / (1.f + expf(-(a + b1[lane])));
        }
    }
    __syncthreads();                                   // B3: s1p ready (last barrier)

    // Tail: warp 0 only
    if (wid == 0) {
        #pragma unroll
        for (int j = 0; j < 6; j++) {
            int idx = lane + 32 * j;
            if (idx < 168) {
                int t2 = idx / 14, c2 = idx - t2 * 14;
                float a = b2[c2];
                #pragma unroll
                for (int kw2 = 0; kw2 < 5; kw2++)
                    #pragma unroll
                    for (int cin = 0; cin < 6; cin++)
                        a += s1p[(t2 + kw2) * 6 + cin] * W2[(kw2 * 6 + cin) * 14 + c2];
                out2s[idx] = a;
            }
        }
        __syncwarp();
        float e2 = 0.f;
        if (lane < 12) {
            #pragma unroll
            for (int c = 0; c < 14; c++) e2 += out2s[lane * 14 + c];
        }
        unsigned e2u = (lane < 12) ? fmono(e2) : 0u;
        int j4r[4];
        #pragma unroll
        for (int r = 0; r < 4; r++) {
            unsigned m = __reduce_max_sync(FULL, e2u);
            int tw = (e2u == m) ? lane : 63;
            int tmin = __reduce_min_sync(FULL, tw);
            j4r[r] = tmin;
            if (lane == tmin) e2u = 0u;
        }
        float mm = 0.f;
        if (lane < 14)
            mm = 0.25f * (out2s[j4r[0] * 14 + lane] + out2s[j4r[1] * 14 + lane] +
                          out2s[j4r[2] * 14 + lane] + out2s[j4r[3] * 14 + lane]) * Wd[lane];
        #pragma unroll
        for (int o = 16; o > 0; o >>= 1) mm += __shfl_xor_sync(FULL, mm, o);

        unsigned old = 0;
        if (lane == 0) {
            g_part[b] = mm + bd[0];
            __threadfence();
            old = atomicInc(&g_ctr, B - 1);            // wraps -> self-reset each replay
        }
        old = __shfl_sync(FULL, old, 0);
        if (old == B - 1) {
            __threadfence();
            float s = 0.f;
            #pragma unroll
            for (int k = 0; k < 8; k++) s += g_part[lane + 32 * k];
            #pragma unroll
            for (int o = 16; o > 0; o >>= 1) s += __shfl_xor_sync(FULL, s, o);
            if (lane == 0) out[0] = 1.f / (1.f + expf(-(s * (1.f / 256.f))));
        }
    }
}

// ---------------------------------------------------------------------------
extern "C" void kernel_launch(void* const* d_in, const int* in_sizes, int n_in,
                              void* d_out, int out_size) {
    const int*   x    = (const int*)  d_in[0];
    const float* emb  = (const float*)d_in[1];
    const float* W1   = (const float*)d_in[2];
    const float* b1   = (const float*)d_in[3];
    const float* W2   = (const float*)d_in[4];
    const float* b2   = (const float*)d_in[5];
    const float* Wd   = (const float*)d_in[6];
    const float* bd   = (const float*)d_in[7];
    float* out = (float*)d_out;

    const size_t smemB = (NW * WSTRIDE + 192 + 192 + 8 + 96 + 168 + 2100)
                         * sizeof(float);                                 // 82064 B
    cudaFuncSetAttribute(dcnn_fused_kernel,
                         cudaFuncAttributeMaxDynamicSharedMemorySize, (int)smemB);

    dcnn_fused_kernel<<<B, NT, smemB>>>(x, emb, W1, b1, W2, b2, Wd, bd, out);
    (void)in_sizes; (void)n_in; (void)out_size;
}